// round 16
// baseline (speedup 1.0000x reference)
#include <cuda_runtime.h>
#include <cuda_fp16.h>
#include <math.h>

#define B 8
#define D 128
#define G 2048
#define L 24
#define GF 1025
#define GFP 1040          // padded ScT row stride
#define BD 1024

// ---------------- scratch (device globals, no allocation) ----------------
__device__ float2  g_stat[B*G];            // (mean, rstd) per (b,g)
__device__ float2  g_Xc[(size_t)GF*BD];    // rfft(z)                [f][b*128+d]
__device__ float2  g_ThT2[L*64*D];         // Theta d-paired         [l][d2][h]
__device__ __half2 g_Wh[(size_t)GF*64*D];  // fp16 W d-paired        [f][d2][h]
__device__ float2  g_ScT[(size_t)BD*GFP];  // spectral out transposed [b*128+h][f]
__device__ float   g_S[B*D*G];             // irfft result           [b][h][g]
__device__ float   g_w1T[D*2*D];           // w1 transposed          [k=128][h=256]
__device__ float   g_w2T[2*D*D];           // w2 transposed          [k=256][d=128]

// ---------------- helpers ----------------
__device__ __forceinline__ unsigned long long splat2(float v) {
    unsigned long long r; unsigned int u = __float_as_uint(v);
    asm("mov.b64 %0, {%1, %2};" : "=l"(r) : "r"(u), "r"(u));
    return r;
}
__device__ __forceinline__ void fma2(unsigned long long& d, unsigned long long a,
                                     unsigned long long b, unsigned long long c) {
    asm("fma.rn.f32x2 %0, %1, %2, %3;" : "=l"(d) : "l"(a), "l"(b), "l"(c));
}
__device__ __forceinline__ float2 unpack2(unsigned long long v) {
    unsigned int lo, hi;
    asm("mov.b64 {%0, %1}, %2;" : "=r"(lo), "=r"(hi) : "l"(v));
    return make_float2(__uint_as_float(lo), __uint_as_float(hi));
}
__device__ __forceinline__ float2 cmul(float2 a, float2 b) {
    return make_float2(a.x * b.x - a.y * b.y, a.x * b.y + a.y * b.x);
}
__device__ __forceinline__ float2 cadd(float2 a, float2 b) { return make_float2(a.x + b.x, a.y + b.y); }
__device__ __forceinline__ float2 csub(float2 a, float2 b) { return make_float2(a.x - b.x, a.y - b.y); }

// ---------------- 2048-pt complex FFT in smem: radix-8 x3 + radix-4, 256 threads ----------------
template<int SGN>
__device__ __forceinline__ float2* fft2048_body(float2* b0, float2* b1,
                                                const float2* tw, int t)
{
    const float R2 = 0.70710678118654752440f;
    const float2 W1 = make_float2(R2, SGN * R2);
    const float2 W3 = make_float2(-R2, SGN * R2);
    float2* src = b0; float2* dst = b1;
#pragma unroll
    for (int s = 0; s < 3; s++) {
        int Ls = 1 << (3 * s);
        int j = t;
        int p = j & (Ls - 1);
        int q = j >> (3 * s);
        float2 u0 = src[j];
        float2 u1 = src[j + 256],  u2 = src[j + 512],  u3 = src[j + 768];
        float2 u4 = src[j + 1024], u5 = src[j + 1280], u6 = src[j + 1536], u7 = src[j + 1792];
        if (s > 0) {
            float2 w1 = tw[p << (8 - 3 * s)];
            float2 w2 = cmul(w1, w1);
            float2 w3 = cmul(w2, w1);
            float2 w4 = cmul(w2, w2);
            float2 w5 = cmul(w4, w1);
            float2 w6 = cmul(w4, w2);
            float2 w7 = cmul(w4, w3);
            u1 = cmul(u1, w1); u2 = cmul(u2, w2); u3 = cmul(u3, w3);
            u4 = cmul(u4, w4); u5 = cmul(u5, w5); u6 = cmul(u6, w6); u7 = cmul(u7, w7);
        }
        float2 es0 = cadd(u0, u4), es1 = csub(u0, u4);
        float2 es2 = cadd(u2, u6), es3 = csub(u2, u6);
        float2 sie = (SGN < 0) ? make_float2(es3.y, -es3.x) : make_float2(-es3.y, es3.x);
        float2 E0 = cadd(es0, es2), E2 = csub(es0, es2);
        float2 E1 = cadd(es1, sie), E3 = csub(es1, sie);
        float2 os0 = cadd(u1, u5), os1 = csub(u1, u5);
        float2 os2 = cadd(u3, u7), os3 = csub(u3, u7);
        float2 sio = (SGN < 0) ? make_float2(os3.y, -os3.x) : make_float2(-os3.y, os3.x);
        float2 O0 = cadd(os0, os2), O2 = csub(os0, os2);
        float2 O1 = cadd(os1, sio), O3 = csub(os1, sio);
        float2 T1 = cmul(W1, O1);
        float2 T2 = (SGN < 0) ? make_float2(O2.y, -O2.x) : make_float2(-O2.y, O2.x);
        float2 T3 = cmul(W3, O3);
        int o = (q << (3 * s + 3)) + p;
        dst[o]          = cadd(E0, O0);
        dst[o + 4 * Ls] = csub(E0, O0);
        dst[o + Ls]     = cadd(E1, T1);
        dst[o + 5 * Ls] = csub(E1, T1);
        dst[o + 2 * Ls] = cadd(E2, T2);
        dst[o + 6 * Ls] = csub(E2, T2);
        dst[o + 3 * Ls] = cadd(E3, T3);
        dst[o + 7 * Ls] = csub(E3, T3);
        __syncthreads();
        float2* tmp = src; src = dst; dst = tmp;
    }
#pragma unroll
    for (int jj = 0; jj < 2; jj++) {
        int j = t + jj * 256;
        float2 t0 = src[j], t1 = src[j + 512], t2 = src[j + 1024], t3 = src[j + 1536];
        float2 w1 = tw[j];
        float2 w2 = tw[2 * j];
        float2 w3 = cmul(w1, w2);
        t1 = cmul(t1, w1); t2 = cmul(t2, w2); t3 = cmul(t3, w3);
        float2 a02 = cadd(t0, t2), s02 = csub(t0, t2);
        float2 a13 = cadd(t1, t3), s13 = csub(t1, t3);
        float2 sis = (SGN < 0) ? make_float2(s13.y, -s13.x) : make_float2(-s13.y, s13.x);
        dst[j]        = cadd(a02, a13);
        dst[j + 512]  = cadd(s02, sis);
        dst[j + 1024] = csub(a02, a13);
        dst[j + 1536] = csub(s02, sis);
    }
    __syncthreads();
    return dst;
}

// ---------------- prep: LN stats + Theta d-paired transpose + weight transposes ----------------
// GRID MUST BE 576: blocks 0-63 stats, 64-447 theta, 448-575 weight transposes.
__global__ void __launch_bounds__(256) prep_kernel(const float* __restrict__ x,
                                                   const float* __restrict__ Theta,
                                                   const float* __restrict__ w1,
                                                   const float* __restrict__ w2)
{
    __shared__ float tile[32][33];
    int blk = blockIdx.x;
    int t   = threadIdx.x;
    if (blk < 64) {
        int idx = blk * 256 + t;
        int b = idx >> 11;
        int g = idx & (G - 1);
        const float* xp = x + (size_t)b * D * G + g;
        float s = 0.f, s2 = 0.f;
#pragma unroll 8
        for (int d = 0; d < D; d++) { float v = xp[d * G]; s += v; s2 += v * v; }
        float mean = s * (1.f / D);
        float var = s2 * (1.f / D) - mean * mean;
        g_stat[idx] = make_float2(mean, rsqrtf(var + 1e-5f));
    } else if (blk < 448) {
        int blk2 = blk - 64;
        int l = blk2 >> 4;
        int rem = blk2 & 15;
        int h0 = (rem & 3) * 32, d0 = (rem >> 2) * 32;
        int tx = t & 31, ty = t >> 5;
        const float* src = Theta + (size_t)l * D * D;
        for (int i = ty; i < 32; i += 8)
            tile[i][tx] = src[(h0 + i) * D + d0 + tx];
        __syncthreads();
        float2* dst = g_ThT2 + (size_t)l * 64 * D;
        for (int i2 = ty; i2 < 16; i2 += 8) {
            int d2 = (d0 >> 1) + i2;
            dst[d2 * D + h0 + tx] = make_float2(tile[tx][2 * i2], tile[tx][2 * i2 + 1]);
        }
    } else {
        int blk3 = blk - 448;
        int z = blk3 >> 6;
        int rem = blk3 & 63;
        const float* src = z ? w2 : w1;
        float* dst = z ? g_w2T : g_w1T;
        int R = z ? 128 : 256, C = z ? 256 : 128;
        int c0 = (rem & 7) * 32, r0 = (rem >> 3) * 32;
        if (c0 >= C || r0 >= R) return;
        int tx = t & 31, ty = t >> 5;
        for (int i = ty; i < 32; i += 8) tile[i][tx] = src[(r0 + i) * C + c0 + tx];
        __syncthreads();
        for (int i = ty; i < 32; i += 8) dst[(c0 + i) * R + r0 + tx] = tile[tx][i];
    }
}

// ---------------- forward FFT (LN fused) + wprep (fp16 W), merged launch ----------------
__global__ void __launch_bounds__(256) fwd_wprep_kernel(const float* __restrict__ x,
                                                        const float* __restrict__ gamma,
                                                        const float* __restrict__ beta,
                                                        const float* __restrict__ Phi)
{
    __shared__ float2 b0[G];
    __shared__ float2 b1[G];
    __shared__ float2 tw[G / 2];
    __shared__ float phis[32][25];
    int blk = blockIdx.x;
    int t   = threadIdx.x;

    if (blk < 512) {
        int b  = blk >> 6;
        int dp = blk & 63;
        int d0c = 2 * dp;
        for (int p = t; p < G / 2; p += 256) {
            float s, c;
            __sincosf(-3.14159265358979323846f * (float)p / 1024.f, &s, &c);
            tw[p] = make_float2(c, s);
        }
        float ga0 = gamma[d0c], ga1 = gamma[d0c + 1];
        float be0 = beta[d0c],  be1 = beta[d0c + 1];
        const float* row0 = x + ((size_t)b * D + d0c) * G;
        const float* row1 = row0 + G;
        const float2* st = g_stat + b * G;
        for (int i = t; i < G; i += 256) {
            float2 s = st[i];
            b0[i] = make_float2((row0[i] - s.x) * s.y * ga0 + be0,
                                (row1[i] - s.x) * s.y * ga1 + be1);
        }
        __syncthreads();
        float2* res = fft2048_body<-1>(b0, b1, tw, t);
        int col = b * D + d0c;
        for (int f = t; f < GF; f += 256) {
            float2 Yf = res[f];
            float2 Yg = res[(G - f) & (G - 1)];
            float2 Xd  = make_float2(0.5f * (Yf.x + Yg.x), 0.5f * (Yf.y - Yg.y));
            float2 Xd1 = make_float2(0.5f * (Yf.y + Yg.y), 0.5f * (Yg.x - Yf.x));
            g_Xc[(size_t)f * BD + col]     = Xd;
            g_Xc[(size_t)f * BD + col + 1] = Xd1;
        }
    } else {
        int fid = blk - 512;
        int f0 = (fid >> 5) * 32;
        int i0 = (fid & 31) * 256;
        for (int k = t; k < 32 * L; k += 256) {
            int fl = k / L, l = k % L;
            int f = f0 + fl;
            phis[fl][l] = (f < GF) ? Phi[l * GF + f] : 0.f;
        }
        __syncthreads();
        float2 th[L];
#pragma unroll
        for (int l = 0; l < L; l++) th[l] = g_ThT2[l * (64 * D) + i0 + t];
        int fmax = GF - f0; if (fmax > 32) fmax = 32;
        for (int fl = 0; fl < fmax; fl++) {
            float2 acc = make_float2(0.f, 0.f);
#pragma unroll
            for (int l = 0; l < L; l++) {
                float p = phis[fl][l];
                acc.x += p * th[l].x;
                acc.y += p * th[l].y;
            }
            g_Wh[(size_t)(f0 + fl) * (64 * D) + i0 + t] = __float22half2_rn(acc);
        }
    }
}

// ---------------- per-frequency complex GEMM: 2 warps per f (split over b), fp16 W ----------------
__global__ void __launch_bounds__(512) specmm_kernel()
{
    __shared__ float2 sm[128][17];
    int t    = threadIdx.x;
    int lane = t & 31;
    int warp = (t >> 5) & 7;
    int bh   = t >> 8;              // 0 -> b 0..3, 1 -> b 4..7
    int f0 = blockIdx.x * 8;
    int f  = f0 + warp;
    int fc = (f < GF) ? f : (GF - 1);     // clamp; extra warps do harmless work
    const ulonglong2* xq = (const ulonglong2*)(g_Xc + (size_t)fc * BD) + bh * 256;
    const uint4* wp = (const uint4*)(g_Wh + (size_t)fc * (64 * D));
    unsigned long long acc[4][4];
#pragma unroll
    for (int b = 0; b < 4; b++)
#pragma unroll
        for (int j = 0; j < 4; j++) acc[b][j] = 0ull;

#pragma unroll 4
    for (int i = 0; i < 64; i++) {          // d2 = i covers d = 2i, 2i+1
        uint4 w = wp[i * 32 + lane];
        const __half2* hh = (const __half2*)&w;
        float2 w0 = __half22float2(hh[0]);
        float2 w1 = __half22float2(hh[1]);
        float2 w2 = __half22float2(hh[2]);
        float2 w3 = __half22float2(hh[3]);
        unsigned long long a0 = splat2(w0.x), c0 = splat2(w0.y);
        unsigned long long a1 = splat2(w1.x), c1 = splat2(w1.y);
        unsigned long long a2 = splat2(w2.x), c2 = splat2(w2.y);
        unsigned long long a3 = splat2(w3.x), c3 = splat2(w3.y);
#pragma unroll
        for (int b = 0; b < 4; b++) {
            ulonglong2 xv = xq[b * 64 + i];
            fma2(acc[b][0], xv.x, a0, acc[b][0]);
            fma2(acc[b][1], xv.x, a1, acc[b][1]);
            fma2(acc[b][2], xv.x, a2, acc[b][2]);
            fma2(acc[b][3], xv.x, a3, acc[b][3]);
            fma2(acc[b][0], xv.y, c0, acc[b][0]);
            fma2(acc[b][1], xv.y, c1, acc[b][1]);
            fma2(acc[b][2], xv.y, c2, acc[b][2]);
            fma2(acc[b][3], xv.y, c3, acc[b][3]);
        }
    }

    int nf = GF - f0; if (nf > 8) nf = 8;
#pragma unroll 1
    for (int bb = 0; bb < 4; bb++) {
        __syncthreads();
#pragma unroll
        for (int j = 0; j < 4; j++)
            sm[lane * 4 + j][warp + 8 * bh] = unpack2(acc[bb][j]);
        __syncthreads();
        if (t < 256) {
            int h    = t & 127;
            int bsel = t >> 7;
            int bglob = bb + 4 * bsel;
            const float2* srow = &sm[h][8 * bsel];
            float2* dst = g_ScT + (size_t)(bglob * 128 + h) * GFP + f0;
            if (nf == 8) {
                float4* d4 = (float4*)dst;
                d4[0] = make_float4(srow[0].x, srow[0].y, srow[1].x, srow[1].y);
                d4[1] = make_float4(srow[2].x, srow[2].y, srow[3].x, srow[3].y);
                d4[2] = make_float4(srow[4].x, srow[4].y, srow[5].x, srow[5].y);
                d4[3] = make_float4(srow[6].x, srow[6].y, srow[7].x, srow[7].y);
            } else {
                for (int k = 0; k < nf; k++) dst[k] = srow[k];
            }
        }
    }
}

// ---------------- inverse FFT: 2 Hermitian spectra packed ----------------
__global__ void __launch_bounds__(256) fft_inv_kernel()
{
    __shared__ float2 b0[G];
    __shared__ float2 b1[G];
    __shared__ float2 tw[G / 2];
    int blk = blockIdx.x;
    int b   = blk >> 6;
    int hp  = blk & 63;
    int t   = threadIdx.x;
    for (int p = t; p < G / 2; p += 256) {
        float s, c;
        __sincosf(3.14159265358979323846f * (float)p / 1024.f, &s, &c);
        tw[p] = make_float2(c, s);
    }
    int col = b * D + 2 * hp;
    const float2* S0p = g_ScT + (size_t)col * GFP;
    const float2* S1p = S0p + GFP;
    for (int f = t; f < GF; f += 256) {
        float2 S0 = S0p[f];
        float2 S1 = S1p[f];
        b0[f] = make_float2(S0.x - S1.y, S0.y + S1.x);
        if (f > 0 && f < G / 2)
            b0[G - f] = make_float2(S0.x + S1.y, S1.x - S0.y);
    }
    __syncthreads();
    float2* res = fft2048_body<1>(b0, b1, tw, t);
    float* out0 = g_S + (size_t)col * G;
    float* out1 = out0 + G;
    const float sc = 1.0f / G;
    for (int g = t; g < G; g += 256) {
        float2 v = res[g];
        out0[g] = v.x * sc;
        out1[g] = v.y * sc;
    }
}

// ---------------- fused MLP (512 threads): out = x + w2 @ gelu(w1 @ S + b1) + b2 ----------------
// Phase1: warp = 16h x 32g, thread = 4h x 4g. Phase2: thread = 2d x 4g.
// Swizzle: Hsh column offset ((h>>2)&7)*4 (write) == ((k>>2)&7)*4 (read).
__global__ void __launch_bounds__(512) mlp_kernel(const float* __restrict__ b1,
                                                  const float* __restrict__ b2,
                                                  const float* __restrict__ x,
                                                  float* __restrict__ out)
{
    __shared__ float Ssh[128][32];
    __shared__ float Hsh[256][32];
    int b  = blockIdx.y;
    int g0 = blockIdx.x * 32;
    int t  = threadIdx.x;

    const float* Sb = g_S + (size_t)b * D * G + g0;
    for (int idx = t; idx < 128 * 8; idx += 512) {
        int k = idx >> 3, c = idx & 7;
        *(float4*)&Ssh[k][c * 4] = *(const float4*)&Sb[(size_t)k * G + c * 4];
    }
    __syncthreads();

    // ---- phase 1: H = gelu(w1 @ S + b1) ----
    int lane = t & 31, warp = t >> 5;      // 16 warps
    int tx = lane & 7;                     // g = tx*4 .. +3
    int hy = lane >> 3;                    // 0..3
    int h0 = warp * 16 + hy * 4;           // 4 h per thread
    unsigned long long acc[4][2];
#pragma unroll
    for (int i = 0; i < 4; i++) { acc[i][0] = 0ull; acc[i][1] = 0ull; }
#pragma unroll 4
    for (int k = 0; k < 128; k++) {
        float4 wa = *(const float4*)&g_w1T[k * 256 + h0];
        unsigned long long s0 = *(const unsigned long long*)&Ssh[k][tx * 4];
        unsigned long long s1 = *(const unsigned long long*)&Ssh[k][tx * 4 + 2];
        float wv[4] = {wa.x, wa.y, wa.z, wa.w};
#pragma unroll
        for (int i = 0; i < 4; i++) {
            unsigned long long ws = splat2(wv[i]);
            fma2(acc[i][0], s0, ws, acc[i][0]);
            fma2(acc[i][1], s1, ws, acc[i][1]);
        }
    }
#pragma unroll
    for (int i = 0; i < 4; i++) {
        int h = h0 + i;
        float bias = b1[h];
        int c0 = (tx * 4 + (((h >> 2) & 7) * 4)) & 31;
        float2 v0 = unpack2(acc[i][0]), v1 = unpack2(acc[i][1]);
        float q0 = v0.x + bias, q1 = v0.y + bias, q2 = v1.x + bias, q3 = v1.y + bias;
        q0 = 0.5f * q0 * (1.f + erff(q0 * 0.7071067811865475f));
        q1 = 0.5f * q1 * (1.f + erff(q1 * 0.7071067811865475f));
        q2 = 0.5f * q2 * (1.f + erff(q2 * 0.7071067811865475f));
        q3 = 0.5f * q3 * (1.f + erff(q3 * 0.7071067811865475f));
        *(float4*)&Hsh[h][c0] = make_float4(q0, q1, q2, q3);
    }
    __syncthreads();

    // ---- phase 2: out = x + w2 @ H + b2 ----
    int tx2 = t & 7;                       // g = tx2*4 .. +3
    int d0 = (t >> 3) * 2;                 // 2 d per thread
    unsigned long long acc2[2][2];
#pragma unroll
    for (int i = 0; i < 2; i++) { acc2[i][0] = 0ull; acc2[i][1] = 0ull; }
#pragma unroll 4
    for (int k = 0; k < 256; k++) {
        float2 wa = *(const float2*)&g_w2T[k * 128 + d0];
        int c0 = (tx2 * 4 + (((k >> 2) & 7) * 4)) & 31;
        unsigned long long h0v = *(const unsigned long long*)&Hsh[k][c0];
        unsigned long long h1v = *(const unsigned long long*)&Hsh[k][c0 + 2];
        unsigned long long ws0 = splat2(wa.x);
        unsigned long long ws1 = splat2(wa.y);
        fma2(acc2[0][0], h0v, ws0, acc2[0][0]);
        fma2(acc2[0][1], h1v, ws0, acc2[0][1]);
        fma2(acc2[1][0], h0v, ws1, acc2[1][0]);
        fma2(acc2[1][1], h1v, ws1, acc2[1][1]);
    }
#pragma unroll
    for (int i = 0; i < 2; i++) {
        int d = d0 + i;
        float bias = b2[d];
        size_t o = ((size_t)b * D + d) * G + g0 + tx2 * 4;
        float2 v0 = unpack2(acc2[i][0]), v1 = unpack2(acc2[i][1]);
        float4 xv = *(const float4*)&x[o];
        *(float4*)&out[o] = make_float4(xv.x + v0.x + bias, xv.y + v0.y + bias,
                                        xv.z + v1.x + bias, xv.w + v1.y + bias);
    }
}

extern "C" void kernel_launch(void* const* d_in, const int* in_sizes, int n_in,
                              void* d_out, int out_size)
{
    const float* x     = (const float*)d_in[0];
    const float* Phi   = (const float*)d_in[1];
    const float* Theta = (const float*)d_in[2];
    const float* gam   = (const float*)d_in[3];
    const float* bet   = (const float*)d_in[4];
    const float* w1    = (const float*)d_in[5];
    const float* b1    = (const float*)d_in[6];
    const float* w2    = (const float*)d_in[7];
    const float* b2    = (const float*)d_in[8];
    float* out = (float*)d_out;

    prep_kernel<<<576, 256>>>(x, Theta, w1, w2);          // 576, NOT 480 — w transposes live in blk 448..575
    fwd_wprep_kernel<<<512 + 33 * 32, 256>>>(x, gam, bet, Phi);
    specmm_kernel<<<129, 512>>>();
    fft_inv_kernel<<<512, 256>>>();
    mlp_kernel<<<dim3(64, 8), 512>>>(b1, b2, x, out);
}

// round 17
// speedup vs baseline: 1.2302x; 1.2302x over previous
#include <cuda_runtime.h>
#include <cuda_fp16.h>
#include <math.h>

#define B 8
#define D 128
#define G 2048
#define L 24
#define GF 1025
#define GFP 1040          // padded ScT row stride
#define BD 1024

// ---------------- scratch (device globals, no allocation) ----------------
__device__ float2  g_stat[B*G];            // (mean, rstd) per (b,g)
__device__ float2  g_Xc[(size_t)GF*BD];    // rfft(z)                [f][b*128+d]
__device__ float2  g_ThT2[L*64*D];         // Theta d-paired         [l][d2][h]
__device__ __half2 g_Wh[(size_t)GF*64*D];  // fp16 W d-paired        [f][d2][h]
__device__ float2  g_ScT[(size_t)BD*GFP];  // spectral out transposed [b*128+h][f]
__device__ float   g_S[B*D*G];             // irfft result           [b][h][g]
__device__ float   g_w1T[D*2*D];           // w1 transposed          [k=128][h=256]
__device__ float   g_w2T[2*D*D];           // w2 transposed          [k=256][d=128]

// ---------------- helpers ----------------
__device__ __forceinline__ unsigned long long splat2(float v) {
    unsigned long long r; unsigned int u = __float_as_uint(v);
    asm("mov.b64 %0, {%1, %2};" : "=l"(r) : "r"(u), "r"(u));
    return r;
}
__device__ __forceinline__ void fma2(unsigned long long& d, unsigned long long a,
                                     unsigned long long b, unsigned long long c) {
    asm("fma.rn.f32x2 %0, %1, %2, %3;" : "=l"(d) : "l"(a), "l"(b), "l"(c));
}
__device__ __forceinline__ float2 unpack2(unsigned long long v) {
    unsigned int lo, hi;
    asm("mov.b64 {%0, %1}, %2;" : "=r"(lo), "=r"(hi) : "l"(v));
    return make_float2(__uint_as_float(lo), __uint_as_float(hi));
}
__device__ __forceinline__ float2 cmul(float2 a, float2 b) {
    return make_float2(a.x * b.x - a.y * b.y, a.x * b.y + a.y * b.x);
}
__device__ __forceinline__ float2 cadd(float2 a, float2 b) { return make_float2(a.x + b.x, a.y + b.y); }
__device__ __forceinline__ float2 csub(float2 a, float2 b) { return make_float2(a.x - b.x, a.y - b.y); }

// ---------------- 2048-pt complex FFT in smem: radix-8 x3 + radix-4, 256 threads ----------------
template<int SGN>
__device__ __forceinline__ float2* fft2048_body(float2* b0, float2* b1,
                                                const float2* tw, int t)
{
    const float R2 = 0.70710678118654752440f;
    const float2 W1 = make_float2(R2, SGN * R2);
    const float2 W3 = make_float2(-R2, SGN * R2);
    float2* src = b0; float2* dst = b1;
#pragma unroll
    for (int s = 0; s < 3; s++) {
        int Ls = 1 << (3 * s);
        int j = t;
        int p = j & (Ls - 1);
        int q = j >> (3 * s);
        float2 u0 = src[j];
        float2 u1 = src[j + 256],  u2 = src[j + 512],  u3 = src[j + 768];
        float2 u4 = src[j + 1024], u5 = src[j + 1280], u6 = src[j + 1536], u7 = src[j + 1792];
        if (s > 0) {
            float2 w1 = tw[p << (8 - 3 * s)];
            float2 w2 = cmul(w1, w1);
            float2 w3 = cmul(w2, w1);
            float2 w4 = cmul(w2, w2);
            float2 w5 = cmul(w4, w1);
            float2 w6 = cmul(w4, w2);
            float2 w7 = cmul(w4, w3);
            u1 = cmul(u1, w1); u2 = cmul(u2, w2); u3 = cmul(u3, w3);
            u4 = cmul(u4, w4); u5 = cmul(u5, w5); u6 = cmul(u6, w6); u7 = cmul(u7, w7);
        }
        float2 es0 = cadd(u0, u4), es1 = csub(u0, u4);
        float2 es2 = cadd(u2, u6), es3 = csub(u2, u6);
        float2 sie = (SGN < 0) ? make_float2(es3.y, -es3.x) : make_float2(-es3.y, es3.x);
        float2 E0 = cadd(es0, es2), E2 = csub(es0, es2);
        float2 E1 = cadd(es1, sie), E3 = csub(es1, sie);
        float2 os0 = cadd(u1, u5), os1 = csub(u1, u5);
        float2 os2 = cadd(u3, u7), os3 = csub(u3, u7);
        float2 sio = (SGN < 0) ? make_float2(os3.y, -os3.x) : make_float2(-os3.y, os3.x);
        float2 O0 = cadd(os0, os2), O2 = csub(os0, os2);
        float2 O1 = cadd(os1, sio), O3 = csub(os1, sio);
        float2 T1 = cmul(W1, O1);
        float2 T2 = (SGN < 0) ? make_float2(O2.y, -O2.x) : make_float2(-O2.y, O2.x);
        float2 T3 = cmul(W3, O3);
        int o = (q << (3 * s + 3)) + p;
        dst[o]          = cadd(E0, O0);
        dst[o + 4 * Ls] = csub(E0, O0);
        dst[o + Ls]     = cadd(E1, T1);
        dst[o + 5 * Ls] = csub(E1, T1);
        dst[o + 2 * Ls] = cadd(E2, T2);
        dst[o + 6 * Ls] = csub(E2, T2);
        dst[o + 3 * Ls] = cadd(E3, T3);
        dst[o + 7 * Ls] = csub(E3, T3);
        __syncthreads();
        float2* tmp = src; src = dst; dst = tmp;
    }
#pragma unroll
    for (int jj = 0; jj < 2; jj++) {
        int j = t + jj * 256;
        float2 t0 = src[j], t1 = src[j + 512], t2 = src[j + 1024], t3 = src[j + 1536];
        float2 w1 = tw[j];
        float2 w2 = tw[2 * j];
        float2 w3 = cmul(w1, w2);
        t1 = cmul(t1, w1); t2 = cmul(t2, w2); t3 = cmul(t3, w3);
        float2 a02 = cadd(t0, t2), s02 = csub(t0, t2);
        float2 a13 = cadd(t1, t3), s13 = csub(t1, t3);
        float2 sis = (SGN < 0) ? make_float2(s13.y, -s13.x) : make_float2(-s13.y, s13.x);
        dst[j]        = cadd(a02, a13);
        dst[j + 512]  = cadd(s02, sis);
        dst[j + 1024] = csub(a02, a13);
        dst[j + 1536] = csub(s02, sis);
    }
    __syncthreads();
    return dst;
}

// ---------------- prep: LN stats + Theta d-paired transpose + weight transposes ----------------
// GRID MUST BE 576: blocks 0-63 stats, 64-447 theta, 448-575 weight transposes.
__global__ void __launch_bounds__(256) prep_kernel(const float* __restrict__ x,
                                                   const float* __restrict__ Theta,
                                                   const float* __restrict__ w1,
                                                   const float* __restrict__ w2)
{
    __shared__ float tile[32][33];
    int blk = blockIdx.x;
    int t   = threadIdx.x;
    if (blk < 64) {
        int idx = blk * 256 + t;
        int b = idx >> 11;
        int g = idx & (G - 1);
        const float* xp = x + (size_t)b * D * G + g;
        float s = 0.f, s2 = 0.f;
#pragma unroll 8
        for (int d = 0; d < D; d++) { float v = xp[d * G]; s += v; s2 += v * v; }
        float mean = s * (1.f / D);
        float var = s2 * (1.f / D) - mean * mean;
        g_stat[idx] = make_float2(mean, rsqrtf(var + 1e-5f));
    } else if (blk < 448) {
        int blk2 = blk - 64;
        int l = blk2 >> 4;
        int rem = blk2 & 15;
        int h0 = (rem & 3) * 32, d0 = (rem >> 2) * 32;
        int tx = t & 31, ty = t >> 5;
        const float* src = Theta + (size_t)l * D * D;
        for (int i = ty; i < 32; i += 8)
            tile[i][tx] = src[(h0 + i) * D + d0 + tx];
        __syncthreads();
        float2* dst = g_ThT2 + (size_t)l * 64 * D;
        for (int i2 = ty; i2 < 16; i2 += 8) {
            int d2 = (d0 >> 1) + i2;
            dst[d2 * D + h0 + tx] = make_float2(tile[tx][2 * i2], tile[tx][2 * i2 + 1]);
        }
    } else {
        int blk3 = blk - 448;
        int z = blk3 >> 6;
        int rem = blk3 & 63;
        const float* src = z ? w2 : w1;
        float* dst = z ? g_w2T : g_w1T;
        int R = z ? 128 : 256, C = z ? 256 : 128;
        int c0 = (rem & 7) * 32, r0 = (rem >> 3) * 32;
        if (c0 >= C || r0 >= R) return;
        int tx = t & 31, ty = t >> 5;
        for (int i = ty; i < 32; i += 8) tile[i][tx] = src[(r0 + i) * C + c0 + tx];
        __syncthreads();
        for (int i = ty; i < 32; i += 8) dst[(c0 + i) * R + r0 + tx] = tile[tx][i];
    }
}

// ---------------- forward FFT (LN fused) + wprep (fp16 W), merged launch ----------------
__global__ void __launch_bounds__(256) fwd_wprep_kernel(const float* __restrict__ x,
                                                        const float* __restrict__ gamma,
                                                        const float* __restrict__ beta,
                                                        const float* __restrict__ Phi)
{
    __shared__ float2 b0[G];
    __shared__ float2 b1[G];
    __shared__ float2 tw[G / 2];
    __shared__ float phis[32][25];
    int blk = blockIdx.x;
    int t   = threadIdx.x;

    if (blk < 512) {
        int b  = blk >> 6;
        int dp = blk & 63;
        int d0c = 2 * dp;
        for (int p = t; p < G / 2; p += 256) {
            float s, c;
            __sincosf(-3.14159265358979323846f * (float)p / 1024.f, &s, &c);
            tw[p] = make_float2(c, s);
        }
        float ga0 = gamma[d0c], ga1 = gamma[d0c + 1];
        float be0 = beta[d0c],  be1 = beta[d0c + 1];
        const float* row0 = x + ((size_t)b * D + d0c) * G;
        const float* row1 = row0 + G;
        const float2* st = g_stat + b * G;
        for (int i = t; i < G; i += 256) {
            float2 s = st[i];
            b0[i] = make_float2((row0[i] - s.x) * s.y * ga0 + be0,
                                (row1[i] - s.x) * s.y * ga1 + be1);
        }
        __syncthreads();
        float2* res = fft2048_body<-1>(b0, b1, tw, t);
        int col = b * D + d0c;
        for (int f = t; f < GF; f += 256) {
            float2 Yf = res[f];
            float2 Yg = res[(G - f) & (G - 1)];
            float2 Xd  = make_float2(0.5f * (Yf.x + Yg.x), 0.5f * (Yf.y - Yg.y));
            float2 Xd1 = make_float2(0.5f * (Yf.y + Yg.y), 0.5f * (Yg.x - Yf.x));
            g_Xc[(size_t)f * BD + col]     = Xd;
            g_Xc[(size_t)f * BD + col + 1] = Xd1;
        }
    } else {
        int fid = blk - 512;
        int f0 = (fid >> 5) * 32;
        int i0 = (fid & 31) * 256;
        for (int k = t; k < 32 * L; k += 256) {
            int fl = k / L, l = k % L;
            int f = f0 + fl;
            phis[fl][l] = (f < GF) ? Phi[l * GF + f] : 0.f;
        }
        __syncthreads();
        float2 th[L];
#pragma unroll
        for (int l = 0; l < L; l++) th[l] = g_ThT2[l * (64 * D) + i0 + t];
        int fmax = GF - f0; if (fmax > 32) fmax = 32;
        for (int fl = 0; fl < fmax; fl++) {
            float2 acc = make_float2(0.f, 0.f);
#pragma unroll
            for (int l = 0; l < L; l++) {
                float p = phis[fl][l];
                acc.x += p * th[l].x;
                acc.y += p * th[l].y;
            }
            g_Wh[(size_t)(f0 + fl) * (64 * D) + i0 + t] = __float22half2_rn(acc);
        }
    }
}

// ---------------- per-frequency complex GEMM: 2 warps per f (split over b), fp16 W ----------------
__global__ void __launch_bounds__(512) specmm_kernel()
{
    __shared__ float2 sm[128][17];
    int t    = threadIdx.x;
    int lane = t & 31;
    int warp = (t >> 5) & 7;
    int bh   = t >> 8;              // 0 -> b 0..3, 1 -> b 4..7
    int f0 = blockIdx.x * 8;
    int f  = f0 + warp;
    int fc = (f < GF) ? f : (GF - 1);     // clamp; extra warps do harmless work
    const ulonglong2* xq = (const ulonglong2*)(g_Xc + (size_t)fc * BD) + bh * 256;
    const uint4* wp = (const uint4*)(g_Wh + (size_t)fc * (64 * D));
    unsigned long long acc[4][4];
#pragma unroll
    for (int b = 0; b < 4; b++)
#pragma unroll
        for (int j = 0; j < 4; j++) acc[b][j] = 0ull;

#pragma unroll 4
    for (int i = 0; i < 64; i++) {          // d2 = i covers d = 2i, 2i+1
        uint4 w = wp[i * 32 + lane];
        const __half2* hh = (const __half2*)&w;
        float2 w0 = __half22float2(hh[0]);
        float2 w1 = __half22float2(hh[1]);
        float2 w2 = __half22float2(hh[2]);
        float2 w3 = __half22float2(hh[3]);
        unsigned long long a0 = splat2(w0.x), c0 = splat2(w0.y);
        unsigned long long a1 = splat2(w1.x), c1 = splat2(w1.y);
        unsigned long long a2 = splat2(w2.x), c2 = splat2(w2.y);
        unsigned long long a3 = splat2(w3.x), c3 = splat2(w3.y);
#pragma unroll
        for (int b = 0; b < 4; b++) {
            ulonglong2 xv = xq[b * 64 + i];
            fma2(acc[b][0], xv.x, a0, acc[b][0]);
            fma2(acc[b][1], xv.x, a1, acc[b][1]);
            fma2(acc[b][2], xv.x, a2, acc[b][2]);
            fma2(acc[b][3], xv.x, a3, acc[b][3]);
            fma2(acc[b][0], xv.y, c0, acc[b][0]);
            fma2(acc[b][1], xv.y, c1, acc[b][1]);
            fma2(acc[b][2], xv.y, c2, acc[b][2]);
            fma2(acc[b][3], xv.y, c3, acc[b][3]);
        }
    }

    int nf = GF - f0; if (nf > 8) nf = 8;
#pragma unroll 1
    for (int bb = 0; bb < 4; bb++) {
        __syncthreads();
#pragma unroll
        for (int j = 0; j < 4; j++)
            sm[lane * 4 + j][warp + 8 * bh] = unpack2(acc[bb][j]);
        __syncthreads();
        if (t < 256) {
            int h    = t & 127;
            int bsel = t >> 7;
            int bglob = bb + 4 * bsel;
            const float2* srow = &sm[h][8 * bsel];
            float2* dst = g_ScT + (size_t)(bglob * 128 + h) * GFP + f0;
            if (nf == 8) {
                float4* d4 = (float4*)dst;
                d4[0] = make_float4(srow[0].x, srow[0].y, srow[1].x, srow[1].y);
                d4[1] = make_float4(srow[2].x, srow[2].y, srow[3].x, srow[3].y);
                d4[2] = make_float4(srow[4].x, srow[4].y, srow[5].x, srow[5].y);
                d4[3] = make_float4(srow[6].x, srow[6].y, srow[7].x, srow[7].y);
            } else {
                for (int k = 0; k < nf; k++) dst[k] = srow[k];
            }
        }
    }
}

// ---------------- inverse FFT: 2 Hermitian spectra packed ----------------
__global__ void __launch_bounds__(256) fft_inv_kernel()
{
    __shared__ float2 b0[G];
    __shared__ float2 b1[G];
    __shared__ float2 tw[G / 2];
    int blk = blockIdx.x;
    int b   = blk >> 6;
    int hp  = blk & 63;
    int t   = threadIdx.x;
    for (int p = t; p < G / 2; p += 256) {
        float s, c;
        __sincosf(3.14159265358979323846f * (float)p / 1024.f, &s, &c);
        tw[p] = make_float2(c, s);
    }
    int col = b * D + 2 * hp;
    const float2* S0p = g_ScT + (size_t)col * GFP;
    const float2* S1p = S0p + GFP;
    for (int f = t; f < GF; f += 256) {
        float2 S0 = S0p[f];
        float2 S1 = S1p[f];
        b0[f] = make_float2(S0.x - S1.y, S0.y + S1.x);
        if (f > 0 && f < G / 2)
            b0[G - f] = make_float2(S0.x + S1.y, S1.x - S0.y);
    }
    __syncthreads();
    float2* res = fft2048_body<1>(b0, b1, tw, t);
    float* out0 = g_S + (size_t)col * G;
    float* out1 = out0 + G;
    const float sc = 1.0f / G;
    for (int g = t; g < G; g += 256) {
        float2 v = res[g];
        out0[g] = v.x * sc;
        out1[g] = v.y * sc;
    }
}

// ---------------- fused MLP (256 threads, R14 geometry + LDS.128 merges) ----------------
__global__ void __launch_bounds__(256) mlp_kernel(const float* __restrict__ b1,
                                                  const float* __restrict__ b2,
                                                  const float* __restrict__ x,
                                                  float* __restrict__ out)
{
    __shared__ float Ssh[128][32];
    __shared__ float Hsh[256][32];
    int b  = blockIdx.y;
    int g0 = blockIdx.x * 32;
    int t  = threadIdx.x;

    const float* Sb = g_S + (size_t)b * D * G + g0;
    for (int idx = t; idx < 128 * 8; idx += 256) {
        int k = idx >> 3, c = idx & 7;
        *(float4*)&Ssh[k][c * 4] = *(const float4*)&Sb[(size_t)k * G + c * 4];
    }
    __syncthreads();

    int lane = t & 31, warp = t >> 5;
    int tx = lane & 7;
    int hy = lane >> 3;
    int h0 = warp * 32 + hy * 8;
    unsigned long long acc[8][2];
#pragma unroll
    for (int i = 0; i < 8; i++) { acc[i][0] = 0ull; acc[i][1] = 0ull; }
#pragma unroll 4
    for (int k = 0; k < 128; k++) {
        float4 wa = *(const float4*)&g_w1T[k * 256 + h0];
        float4 wb = *(const float4*)&g_w1T[k * 256 + h0 + 4];
        ulonglong2 sv = *(const ulonglong2*)&Ssh[k][tx * 4];   // one LDS.128
        float wv[8] = {wa.x, wa.y, wa.z, wa.w, wb.x, wb.y, wb.z, wb.w};
#pragma unroll
        for (int i = 0; i < 8; i++) {
            unsigned long long ws = splat2(wv[i]);
            fma2(acc[i][0], sv.x, ws, acc[i][0]);
            fma2(acc[i][1], sv.y, ws, acc[i][1]);
        }
    }
#pragma unroll
    for (int i = 0; i < 8; i++) {
        int h = h0 + i;
        float bias = b1[h];
        int c0 = (tx * 4 + (((h >> 3) & 7) * 4)) & 31;
        float2 v0 = unpack2(acc[i][0]), v1 = unpack2(acc[i][1]);
        float q0 = v0.x + bias, q1 = v0.y + bias, q2 = v1.x + bias, q3 = v1.y + bias;
        q0 = 0.5f * q0 * (1.f + erff(q0 * 0.7071067811865475f));
        q1 = 0.5f * q1 * (1.f + erff(q1 * 0.7071067811865475f));
        q2 = 0.5f * q2 * (1.f + erff(q2 * 0.7071067811865475f));
        q3 = 0.5f * q3 * (1.f + erff(q3 * 0.7071067811865475f));
        *(float4*)&Hsh[h][c0] = make_float4(q0, q1, q2, q3);
    }
    __syncthreads();

    int tx2 = t & 7;
    int d0 = (t >> 3) * 4;
    unsigned long long acc2[4][2];
#pragma unroll
    for (int i = 0; i < 4; i++) { acc2[i][0] = 0ull; acc2[i][1] = 0ull; }
#pragma unroll 4
    for (int k = 0; k < 256; k++) {
        float4 wa = *(const float4*)&g_w2T[k * 128 + d0];
        int c0 = (tx2 * 4 + (((k >> 3) & 7) * 4)) & 31;
        ulonglong2 hv = *(const ulonglong2*)&Hsh[k][c0];       // one LDS.128
        float wv[4] = {wa.x, wa.y, wa.z, wa.w};
#pragma unroll
        for (int i = 0; i < 4; i++) {
            unsigned long long ws = splat2(wv[i]);
            fma2(acc2[i][0], hv.x, ws, acc2[i][0]);
            fma2(acc2[i][1], hv.y, ws, acc2[i][1]);
        }
    }
#pragma unroll
    for (int i = 0; i < 4; i++) {
        int d = d0 + i;
        float bias = b2[d];
        size_t o = ((size_t)b * D + d) * G + g0 + tx2 * 4;
        float2 v0 = unpack2(acc2[i][0]), v1 = unpack2(acc2[i][1]);
        float4 xv = *(const float4*)&x[o];
        *(float4*)&out[o] = make_float4(xv.x + v0.x + bias, xv.y + v0.y + bias,
                                        xv.z + v1.x + bias, xv.w + v1.y + bias);
    }
}

extern "C" void kernel_launch(void* const* d_in, const int* in_sizes, int n_in,
                              void* d_out, int out_size)
{
    const float* x     = (const float*)d_in[0];
    const float* Phi   = (const float*)d_in[1];
    const float* Theta = (const float*)d_in[2];
    const float* gam   = (const float*)d_in[3];
    const float* bet   = (const float*)d_in[4];
    const float* w1    = (const float*)d_in[5];
    const float* b1    = (const float*)d_in[6];
    const float* w2    = (const float*)d_in[7];
    const float* b2    = (const float*)d_in[8];
    float* out = (float*)d_out;

    prep_kernel<<<576, 256>>>(x, Theta, w1, w2);          // 576, NOT 480 — w transposes live in blk 448..575
    fwd_wprep_kernel<<<512 + 33 * 32, 256>>>(x, gam, bet, Phi);
    specmm_kernel<<<129, 512>>>();
    fft_inv_kernel<<<512, 256>>>();
    mlp_kernel<<<dim3(64, 8), 256>>>(b1, b2, x, out);
}